// round 14
// baseline (speedup 1.0000x reference)
#include <cuda_runtime.h>
#include <cuda_fp16.h>
#include <cstdint>

// Problem constants
#define Bb 4
#define Ll 4096
#define Dd 2048
#define Hh 8
#define BLt (Bb*Ll)          // 16384 tokens
#define BD  (Bb*Dd)          // 8192 channels
#define CHUNKS 32
#define CLEN (Ll/CHUNKS)     // 128

// Scratch
__device__ float  g_a[(size_t)BLt * Dd];            // 134 MB (a, fp32 — precision-critical)
__device__ __half g_nx[(size_t)BLt * Dd];           // 67 MB (normalized x, fp16)
__device__ __half g_wTh[16 * 256 * 256];            // [head][gate*256+j][k] K-major fp16
__device__ float  g_sp[Dd];                         // softplus(a_param)
__device__ float  g_chunkA[CHUNKS * BD];
__device__ float  g_chunkH[CHUNKS * BD];

__device__ __forceinline__ uint32_t smem_u32(const void* p) {
    uint32_t a;
    asm("{ .reg .u64 t; cvta.to.shared.u64 t, %1; cvt.u32.u64 %0, t; }" : "=r"(a) : "l"(p));
    return a;
}
#define SWZ128(o) ((o) ^ (((o) >> 3) & 0x70))

__device__ __forceinline__ uint32_t h2u(__half2 h) {
    union { __half2 h; uint32_t u; } cvt;
    cvt.h = h;
    return cvt.u;
}

__device__ __forceinline__ void cp16(uint32_t saddr, const void* g) {
    asm volatile("cp.async.cg.shared.global [%0], [%1], 16;" :: "r"(saddr), "l"(g));
}

__device__ __forceinline__ void ldsm4(uint32_t* r, uint32_t addr) {
    asm volatile("ldmatrix.sync.aligned.m8n8.x4.shared.b16 {%0,%1,%2,%3}, [%4];"
        : "=r"(r[0]), "=r"(r[1]), "=r"(r[2]), "=r"(r[3]) : "r"(addr));
}

__device__ __forceinline__ void mma_f16(float c[4], const uint32_t a[4], uint32_t b0, uint32_t b1) {
    asm volatile(
        "mma.sync.aligned.m16n8k16.row.col.f32.f16.f16.f32 "
        "{%0,%1,%2,%3}, {%4,%5,%6,%7}, {%8,%9}, {%0,%1,%2,%3};"
        : "+f"(c[0]), "+f"(c[1]), "+f"(c[2]), "+f"(c[3])
        : "r"(a[0]), "r"(a[1]), "r"(a[2]), "r"(a[3]), "r"(b0), "r"(b1));
}

__device__ __forceinline__ float tanha(float v) {
    float r;
    asm("tanh.approx.f32 %0, %1;" : "=f"(r) : "f"(v));
    return r;
}

// ---------------------------------------------------------------------------
// Prep: transpose weights to K-major fp16 [h][gate*256+j][k]; softplus.
// ---------------------------------------------------------------------------
__global__ void prep_kernel(const float* __restrict__ ig_w, const float* __restrict__ ag_w,
                            const float* __restrict__ a_param)
{
    __shared__ float t[32][33];
    int bid = blockIdx.x;
    int mat = bid >> 6;                // head*2 + gate
    int tile = bid & 63;
    int tj = tile & 7, tk = tile >> 3;
    int head = mat >> 1, gate = mat & 1;
    const float* w = (gate ? ag_w : ig_w) + head * 65536;
    int tx = threadIdx.x & 31, ty = threadIdx.x >> 5;   // 32 x 8

    #pragma unroll
    for (int r = 0; r < 4; ++r)
        t[ty + r * 8][tx] = w[(tk * 32 + ty + r * 8) * 256 + tj * 32 + tx];
    __syncthreads();
    #pragma unroll
    for (int r = 0; r < 4; ++r) {
        int j = tj * 32 + ty + r * 8;
        g_wTh[(size_t)(head * 512 + gate * 256 + j) * 256 + tk * 32 + tx] = __float2half(t[tx][ty + r * 8]);
    }
    if (bid == 0) {
        for (int d = threadIdx.x; d < Dd; d += 256)
            g_sp[d] = log1pf(__expf(a_param[d]));
    }
}

// ---------------------------------------------------------------------------
// Gates: fp16 mma. A (x, fp32 gmem) loaded upfront into 4 fp16 smem stages
// via LDG+cvt+STS (no xconv kernel). B double-buffered via cp.async.
// K order ends at kt==jslab so that A stage feeds the epilogue's x reads.
// z staged fp32 into the dead A/B stages. Fused elementwise + chunk scan.
// ---------------------------------------------------------------------------
#define OFF_B0 65536
#define SMEM_TOTAL 98304

__global__ __launch_bounds__(256, 2)
void gates_kernel(const float* __restrict__ x,
                  const float* __restrict__ ig_b, const float* __restrict__ ag_b)
{
    extern __shared__ char smem[];
    const uint32_t sb = smem_u32(smem);
    const int tid  = threadIdx.x;
    const int warp = tid >> 5, lane = tid & 31;
    const int grp = lane >> 2, lq = lane & 3;
    const int head  = blockIdx.x >> 2;
    const int jslab = blockIdx.x & 3;      // 64 j-cols per slab
    const int m0    = blockIdx.y * 128;
    const int warpM = warp >> 2;           // 0..1
    const int warpN = warp & 3;            // 0..3 : gate = warpN>>1, njb = (warpN&1)*32

    const int lr = lane & 15, lc = (lane >> 4) * 16;
    const int k0 = (jslab + 1) & 3, k1 = (jslab + 2) & 3, k2 = (jslab + 3) & 3;

    float c[4][4][4];
    #pragma unroll
    for (int i = 0; i < 4; ++i)
        #pragma unroll
        for (int j = 0; j < 4; ++j)
            #pragma unroll
            for (int k = 0; k < 4; ++k) c[i][j][k] = 0.f;

    const float* xbase = x + (size_t)m0 * Dd + head * 256;
    const __half* wbase = g_wTh + (size_t)head * 512 * 256;

    auto load_B = [&](int st, int kt) {
        uint32_t bb = sb + OFF_B0 + st * 16384;
        #pragma unroll
        for (int i = 0; i < 4; ++i) {
            int idx = tid + i * 256;            // 0..1023
            int n = idx >> 3, c16 = idx & 7;
            int wrow = (n >> 6) * 256 + jslab * 64 + (n & 63);
            cp16(bb + SWZ128(n * 128 + c16 * 16), wbase + (size_t)wrow * 256 + kt * 64 + c16 * 8);
        }
        asm volatile("cp.async.commit_group;");
    };

    auto load_A = [&](int kt) {       // fp32 LDG -> fp16 STS, stage kt
        uint32_t ab = sb + kt * 16384;
        const float* xs = xbase + kt * 64;
        #pragma unroll
        for (int i = 0; i < 8; ++i) {
            int idx = tid + i * 256;            // 0..2047 float4 units
            int r = idx >> 4, c4 = idx & 15;
            float4 v = *(const float4*)(xs + (size_t)r * Dd + c4 * 4);
            uint32_t lo = h2u(__floats2half2_rn(v.x, v.y));
            uint32_t hi = h2u(__floats2half2_rn(v.z, v.w));
            asm volatile("st.shared.v2.u32 [%0], {%1,%2};"
                :: "r"(ab + SWZ128((uint32_t)(r * 128 + c4 * 8))), "r"(lo), "r"(hi));
        }
    };

    // B pipeline first (starts DRAM/L2 early), then all A stages.
    load_B(0, k0);
    load_B(1, k1);
    load_A(k0); load_A(k1); load_A(k2); load_A(jslab);
    __syncthreads();    // A visible to all warps

    #pragma unroll 1
    for (int i = 0; i < 4; ++i) {
        int kt = (jslab + 1 + i) & 3;
        int st = i & 1;
        if (i < 3) asm volatile("cp.async.wait_group 1;");
        else       asm volatile("cp.async.wait_group 0;");
        __syncthreads();

        uint32_t sA = sb + kt * 16384;
        uint32_t sB = sb + OFF_B0 + st * 16384;
        #pragma unroll
        for (int k16 = 0; k16 < 4; ++k16) {
            uint32_t a[4][4], b[2][4];
            #pragma unroll
            for (int mt = 0; mt < 4; ++mt)
                ldsm4(a[mt], sA + SWZ128((uint32_t)((warpM * 64 + mt * 16 + lr) * 128 + k16 * 32 + lc)));
            #pragma unroll
            for (int p = 0; p < 2; ++p)
                ldsm4(b[p], sB + SWZ128((uint32_t)((warpN * 32 + p * 16 + lr) * 128 + k16 * 32 + lc)));
            #pragma unroll
            for (int mt = 0; mt < 4; ++mt)
                #pragma unroll
                for (int nt = 0; nt < 4; ++nt)
                    mma_f16(c[mt][nt], a[mt], b[nt >> 1][nt & 1], b[nt >> 1][(nt & 1) + 2]);
        }
        __syncthreads();
        if (i + 2 < 4) load_B(st, (jslab + 3 + i) & 3);
    }

    // z regions (fp32, 16KB each, 128B SWZ rows of 32 j-cols):
    //   (gate0,h0)->A[k0], (gate0,h1)->A[k1], (gate1,h0)->A[k2], (gate1,h1)->B0
    // seg buffer -> B1. A[jslab] preserved for epilogue x.
    uint32_t zreg[2][2];
    zreg[0][0] = sb + k0 * 16384;
    zreg[0][1] = sb + k1 * 16384;
    zreg[1][0] = sb + k2 * 16384;
    zreg[1][1] = sb + OFF_B0;
    const uint32_t segb = sb + OFF_B0 + 16384;

    // Pre-read epilogue x (fp16) from A stage jslab into regs (2 rows / u32).
    uint32_t xr[16];
    {
        const int s  = tid >> 6;
        const int j0 = tid & 63;
        #pragma unroll
        for (int q = 0; q < 16; ++q) {
            int r0 = s * 32 + 2 * q;
            uint32_t lo, hi;
            asm volatile("ld.shared.u16 %0, [%1];" : "=r"(lo)
                : "r"(sb + jslab * 16384 + SWZ128((uint32_t)(r0 * 128 + j0 * 2))));
            asm volatile("ld.shared.u16 %0, [%1];" : "=r"(hi)
                : "r"(sb + jslab * 16384 + SWZ128((uint32_t)((r0 + 1) * 128 + j0 * 2))));
            xr[q] = lo | (hi << 16);
        }
    }

    // Stage z (fp32) into the overlay regions.
    {
        int gate = warpN >> 1;
        int njb  = (warpN & 1) * 32;
        #pragma unroll
        for (int mt = 0; mt < 4; ++mt) {
            #pragma unroll
            for (int nt = 0; nt < 4; ++nt) {
                int row = warpM * 64 + mt * 16 + grp;
                int j   = njb + nt * 8 + 2 * lq;
                uint32_t base = zreg[gate][j >> 5];
                uint32_t off0 = SWZ128((uint32_t)(row * 128 + (j & 31) * 4));
                uint32_t off1 = SWZ128((uint32_t)((row + 8) * 128 + (j & 31) * 4));
                asm volatile("st.shared.v2.f32 [%0], {%1,%2};"
                    :: "r"(base + off0), "f"(c[mt][nt][0]), "f"(c[mt][nt][1]));
                asm volatile("st.shared.v2.f32 [%0], {%1,%2};"
                    :: "r"(base + off1), "f"(c[mt][nt][2]), "f"(c[mt][nt][3]));
            }
        }
    }
    __syncthreads();

    // Fused elementwise + per-segment scan (32 contiguous rows per thread).
    {
        const int s  = tid >> 6;          // segment 0..3
        const int j0 = tid & 63;
        const int d  = head * 256 + jslab * 64 + j0;
        const float bi = ig_b[d];
        const float ba = ag_b[d];
        const float sp8 = -8.f * g_sp[d];
        const float L2E = 1.44269504088896f;
        const uint32_t zi_base = zreg[0][j0 >> 5];
        const uint32_t za_base = zreg[1][j0 >> 5];
        const uint32_t joff = (j0 & 31) * 4;
        float* ga_out = g_a + (size_t)(m0 + s * 32) * Dd + d;
        __half* nx_out = g_nx + (size_t)(m0 + s * 32) * Dd + d;
        float A = 1.f, h = 0.f;
        #pragma unroll 4
        for (int it = 0; it < 32; ++it) {
            int row = s * 32 + it;
            float zi, za;
            asm volatile("ld.shared.f32 %0, [%1];" : "=f"(zi)
                : "r"(zi_base + SWZ128((uint32_t)(row * 128 + joff))));
            asm volatile("ld.shared.f32 %0, [%1];" : "=f"(za)
                : "r"(za_base + SWZ128((uint32_t)(row * 128 + joff))));
            zi += bi; za += ba;
            float gx = fmaf(tanha(0.5f * zi), 0.5f, 0.5f);
            float ga = fmaf(tanha(0.5f * za), 0.5f, 0.5f);
            float la = ga * sp8;
            float a, mult;
            asm("ex2.approx.f32 %0, %1;" : "=f"(a) : "f"(la * L2E));
            float m2 = fmaxf(fmaf(-a, a, 1.f), 0.f);
            asm("sqrt.approx.f32 %0, %1;" : "=f"(mult) : "f"(m2));
            uint32_t xbits = (xr[it >> 1] >> ((it & 1) * 16)) & 0xFFFFu;
            float xv = __half2float(__ushort_as_half((unsigned short)xbits));
            __half nxh = __float2half_rn(xv * gx * mult);
            float nx = __half2float(nxh);    // rounded value, consistent with scan
            ga_out[(size_t)it * Dd] = a;
            nx_out[(size_t)it * Dd] = nxh;
            h = fmaf(a, h, nx);
            A *= a;
        }
        float2* sseg = (float2*)(smem + (segb - sb));
        sseg[s * 64 + j0] = make_float2(A, h);
    }
    __syncthreads();
    if (tid < 64) {
        float2* sseg = (float2*)(smem + (segb - sb));
        float2 s0 = sseg[tid], s1 = sseg[64 + tid], s2 = sseg[128 + tid], s3 = sseg[192 + tid];
        float Ac = s0.x * s1.x * s2.x * s3.x;
        float hc = fmaf(s3.x, fmaf(s2.x, fmaf(s1.x, s0.y, s1.y), s2.y), s3.y);
        int b  = m0 >> 12;
        int ci = (m0 & 4095) >> 7;
        int dd = head * 256 + jslab * 64 + tid;
        g_chunkA[ci * BD + b * Dd + dd] = Ac;
        g_chunkH[ci * BD + b * Dd + dd] = hc;
    }
}

// ---------------------------------------------------------------------------
// Final scan: inline chunk-prefix (batched loads) + streaming chunk scan.
// ---------------------------------------------------------------------------
__global__ void scan_part3(const float* __restrict__ hidden, float* __restrict__ y,
                           float* __restrict__ hfinal, int write_h)
{
    int g  = blockIdx.x * blockDim.x + threadIdx.x;
    int ci = g / BD;                      // uniform within block
    int ch = g % BD;
    int b = ch / Dd, d = ch % Dd;

    // chunk-prefix: h at start of chunk ci
    float h = hidden[ch];
    {
        int k = 0;
        for (; k + 4 <= ci; k += 4) {
            float a0 = g_chunkA[(k+0) * BD + ch], h0 = g_chunkH[(k+0) * BD + ch];
            float a1 = g_chunkA[(k+1) * BD + ch], h1 = g_chunkH[(k+1) * BD + ch];
            float a2 = g_chunkA[(k+2) * BD + ch], h2 = g_chunkH[(k+2) * BD + ch];
            float a3 = g_chunkA[(k+3) * BD + ch], h3 = g_chunkH[(k+3) * BD + ch];
            h = fmaf(a0, h, h0);
            h = fmaf(a1, h, h1);
            h = fmaf(a2, h, h2);
            h = fmaf(a3, h, h3);
        }
        for (; k < ci; ++k)
            h = fmaf(g_chunkA[k * BD + ch], h, g_chunkH[k * BD + ch]);
    }

    size_t off = ((size_t)(b * Ll + ci * CLEN)) * Dd + d;
    const float* pa = g_a + off;
    const __half* pn = g_nx + off;
    float* yp = y + off;

    float ca[8], cn[8];
    #pragma unroll
    for (int i = 0; i < 8; ++i) {
        ca[i] = pa[(size_t)i * Dd];
        cn[i] = __half2float(pn[(size_t)i * Dd]);
    }
    #pragma unroll 1
    for (int base = 0; base < CLEN; base += 8) {
        float na[8], nn[8];
        if (base + 8 < CLEN) {
            #pragma unroll
            for (int i = 0; i < 8; ++i) {
                na[i] = pa[(size_t)(base + 8 + i) * Dd];
                nn[i] = __half2float(pn[(size_t)(base + 8 + i) * Dd]);
            }
        } else {
            #pragma unroll
            for (int i = 0; i < 8; ++i) { na[i] = 0.f; nn[i] = 0.f; }
        }
        #pragma unroll
        for (int i = 0; i < 8; ++i) {
            h = fmaf(ca[i], h, cn[i]);
            yp[(size_t)(base + i) * Dd] = h;
        }
        #pragma unroll
        for (int i = 0; i < 8; ++i) { ca[i] = na[i]; cn[i] = nn[i]; }
    }

    if (write_h && ci == CHUNKS - 1) hfinal[ch] = h;
}

extern "C" void kernel_launch(void* const* d_in, const int* in_sizes, int n_in,
                              void* d_out, int out_size)
{
    const float* x        = (const float*)d_in[0];
    const float* hidden   = (const float*)d_in[1];
    const float* a_param  = (const float*)d_in[2];
    const float* ig_w     = (const float*)d_in[3];
    const float* ig_b     = (const float*)d_in[4];
    const float* ag_w     = (const float*)d_in[5];
    const float* ag_b     = (const float*)d_in[6];
    float* y = (float*)d_out;

    int write_h = (out_size >= BLt * Dd + BD) ? 1 : 0;
    float* hf = y + (size_t)BLt * Dd;

    cudaFuncSetAttribute(gates_kernel, cudaFuncAttributeMaxDynamicSharedMemorySize, SMEM_TOTAL);

    prep_kernel<<<1024, 256>>>(ig_w, ag_w, a_param);
    gates_kernel<<<dim3(32, 128), 256, SMEM_TOTAL>>>(x, ig_b, ag_b);
    scan_part3<<<(BD * CHUNKS) / 256, 256>>>(hidden, y, hf, write_h);
}

// round 15
// speedup vs baseline: 1.0028x; 1.0028x over previous
#include <cuda_runtime.h>
#include <cuda_fp16.h>
#include <cstdint>

// Problem constants
#define Bb 4
#define Ll 4096
#define Dd 2048
#define Hh 8
#define BLt (Bb*Ll)          // 16384 tokens
#define BD  (Bb*Dd)          // 8192 channels
#define CHUNKS 32
#define CLEN (Ll/CHUNKS)     // 128

// Scratch
__device__ float  g_a[(size_t)BLt * Dd];            // 134 MB (a, fp32 — precision-critical)
__device__ __half g_nx[(size_t)BLt * Dd];           // 67 MB (normalized x, fp16)
__device__ __half g_wTh[16 * 256 * 256];            // [head][gate*256+j][k] K-major fp16
__device__ float  g_sp[Dd];                         // softplus(a_param)
__device__ float  g_chunkA[CHUNKS * BD];
__device__ float  g_chunkH[CHUNKS * BD];

__device__ __forceinline__ uint32_t smem_u32(const void* p) {
    uint32_t a;
    asm("{ .reg .u64 t; cvta.to.shared.u64 t, %1; cvt.u32.u64 %0, t; }" : "=r"(a) : "l"(p));
    return a;
}
#define SWZ128(o) ((o) ^ (((o) >> 3) & 0x70))

__device__ __forceinline__ uint32_t h2u(__half2 h) {
    union { __half2 h; uint32_t u; } cvt;
    cvt.h = h;
    return cvt.u;
}

__device__ __forceinline__ void cp16(uint32_t saddr, const void* g) {
    asm volatile("cp.async.cg.shared.global [%0], [%1], 16;" :: "r"(saddr), "l"(g));
}

__device__ __forceinline__ void ldsm4(uint32_t* r, uint32_t addr) {
    asm volatile("ldmatrix.sync.aligned.m8n8.x4.shared.b16 {%0,%1,%2,%3}, [%4];"
        : "=r"(r[0]), "=r"(r[1]), "=r"(r[2]), "=r"(r[3]) : "r"(addr));
}

__device__ __forceinline__ void mma_f16(float c[4], const uint32_t a[4], uint32_t b0, uint32_t b1) {
    asm volatile(
        "mma.sync.aligned.m16n8k16.row.col.f32.f16.f16.f32 "
        "{%0,%1,%2,%3}, {%4,%5,%6,%7}, {%8,%9}, {%0,%1,%2,%3};"
        : "+f"(c[0]), "+f"(c[1]), "+f"(c[2]), "+f"(c[3])
        : "r"(a[0]), "r"(a[1]), "r"(a[2]), "r"(a[3]), "r"(b0), "r"(b1));
}

__device__ __forceinline__ float tanha(float v) {
    float r;
    asm("tanh.approx.f32 %0, %1;" : "=f"(r) : "f"(v));
    return r;
}

// ---------------------------------------------------------------------------
// Prep: transpose weights to K-major fp16 [h][gate*256+j][k]; softplus.
// ---------------------------------------------------------------------------
__global__ void prep_kernel(const float* __restrict__ ig_w, const float* __restrict__ ag_w,
                            const float* __restrict__ a_param)
{
    __shared__ float t[32][33];
    int bid = blockIdx.x;
    int mat = bid >> 6;                // head*2 + gate
    int tile = bid & 63;
    int tj = tile & 7, tk = tile >> 3;
    int head = mat >> 1, gate = mat & 1;
    const float* w = (gate ? ag_w : ig_w) + head * 65536;
    int tx = threadIdx.x & 31, ty = threadIdx.x >> 5;   // 32 x 8

    #pragma unroll
    for (int r = 0; r < 4; ++r)
        t[ty + r * 8][tx] = w[(tk * 32 + ty + r * 8) * 256 + tj * 32 + tx];
    __syncthreads();
    #pragma unroll
    for (int r = 0; r < 4; ++r) {
        int j = tj * 32 + ty + r * 8;
        g_wTh[(size_t)(head * 512 + gate * 256 + j) * 256 + tk * 32 + tx] = __float2half(t[tx][ty + r * 8]);
    }
    if (bid == 0) {
        for (int d = threadIdx.x; d < Dd; d += 256)
            g_sp[d] = log1pf(__expf(a_param[d]));
    }
}

// ---------------------------------------------------------------------------
// Gates: fp16 mma. A (x, fp32 gmem) loaded upfront into 4 fp16 smem stages
// via LDG+cvt+STS (no xconv kernel). B double-buffered via cp.async.
// K order ends at kt==jslab so that A stage feeds the epilogue's x reads.
// z staged fp32 into the dead A/B stages. Fused elementwise + chunk scan.
// ---------------------------------------------------------------------------
#define OFF_B0 65536
#define SMEM_TOTAL 98304

__global__ __launch_bounds__(256, 2)
void gates_kernel(const float* __restrict__ x,
                  const float* __restrict__ ig_b, const float* __restrict__ ag_b)
{
    extern __shared__ char smem[];
    const uint32_t sb = smem_u32(smem);
    const int tid  = threadIdx.x;
    const int warp = tid >> 5, lane = tid & 31;
    const int grp = lane >> 2, lq = lane & 3;
    const int head  = blockIdx.x >> 2;
    const int jslab = blockIdx.x & 3;      // 64 j-cols per slab
    const int m0    = blockIdx.y * 128;
    const int warpM = warp >> 2;           // 0..1
    const int warpN = warp & 3;            // 0..3 : gate = warpN>>1, njb = (warpN&1)*32

    const int lr = lane & 15, lc = (lane >> 4) * 16;
    const int k0 = (jslab + 1) & 3, k1 = (jslab + 2) & 3, k2 = (jslab + 3) & 3;

    float c[4][4][4];
    #pragma unroll
    for (int i = 0; i < 4; ++i)
        #pragma unroll
        for (int j = 0; j < 4; ++j)
            #pragma unroll
            for (int k = 0; k < 4; ++k) c[i][j][k] = 0.f;

    const float* xbase = x + (size_t)m0 * Dd + head * 256;
    const __half* wbase = g_wTh + (size_t)head * 512 * 256;

    auto load_B = [&](int st, int kt) {
        uint32_t bb = sb + OFF_B0 + st * 16384;
        #pragma unroll
        for (int i = 0; i < 4; ++i) {
            int idx = tid + i * 256;            // 0..1023
            int n = idx >> 3, c16 = idx & 7;
            int wrow = (n >> 6) * 256 + jslab * 64 + (n & 63);
            cp16(bb + SWZ128(n * 128 + c16 * 16), wbase + (size_t)wrow * 256 + kt * 64 + c16 * 8);
        }
        asm volatile("cp.async.commit_group;");
    };

    auto load_A = [&](int kt) {       // fp32 LDG -> fp16 STS, stage kt
        uint32_t ab = sb + kt * 16384;
        const float* xs = xbase + kt * 64;
        #pragma unroll
        for (int i = 0; i < 8; ++i) {
            int idx = tid + i * 256;            // 0..2047 float4 units
            int r = idx >> 4, c4 = idx & 15;
            float4 v = *(const float4*)(xs + (size_t)r * Dd + c4 * 4);
            uint32_t lo = h2u(__floats2half2_rn(v.x, v.y));
            uint32_t hi = h2u(__floats2half2_rn(v.z, v.w));
            asm volatile("st.shared.v2.u32 [%0], {%1,%2};"
                :: "r"(ab + SWZ128((uint32_t)(r * 128 + c4 * 8))), "r"(lo), "r"(hi));
        }
    };

    // B pipeline first (starts DRAM/L2 early), then all A stages.
    load_B(0, k0);
    load_B(1, k1);
    load_A(k0); load_A(k1); load_A(k2); load_A(jslab);
    __syncthreads();    // A visible to all warps

    #pragma unroll 1
    for (int i = 0; i < 4; ++i) {
        int kt = (jslab + 1 + i) & 3;
        int st = i & 1;
        if (i < 3) asm volatile("cp.async.wait_group 1;");
        else       asm volatile("cp.async.wait_group 0;");
        __syncthreads();

        uint32_t sA = sb + kt * 16384;
        uint32_t sB = sb + OFF_B0 + st * 16384;
        #pragma unroll
        for (int k16 = 0; k16 < 4; ++k16) {
            uint32_t a[4][4], b[2][4];
            #pragma unroll
            for (int mt = 0; mt < 4; ++mt)
                ldsm4(a[mt], sA + SWZ128((uint32_t)((warpM * 64 + mt * 16 + lr) * 128 + k16 * 32 + lc)));
            #pragma unroll
            for (int p = 0; p < 2; ++p)
                ldsm4(b[p], sB + SWZ128((uint32_t)((warpN * 32 + p * 16 + lr) * 128 + k16 * 32 + lc)));
            #pragma unroll
            for (int mt = 0; mt < 4; ++mt)
                #pragma unroll
                for (int nt = 0; nt < 4; ++nt)
                    mma_f16(c[mt][nt], a[mt], b[nt >> 1][nt & 1], b[nt >> 1][(nt & 1) + 2]);
        }
        __syncthreads();
        if (i + 2 < 4) load_B(st, (jslab + 3 + i) & 3);
    }

    // z regions (fp32, 16KB each, 128B SWZ rows of 32 j-cols):
    //   (gate0,h0)->A[k0], (gate0,h1)->A[k1], (gate1,h0)->A[k2], (gate1,h1)->B0
    // seg buffer -> B1. A[jslab] preserved for epilogue x.
    uint32_t zreg[2][2];
    zreg[0][0] = sb + k0 * 16384;
    zreg[0][1] = sb + k1 * 16384;
    zreg[1][0] = sb + k2 * 16384;
    zreg[1][1] = sb + OFF_B0;
    const uint32_t segb = sb + OFF_B0 + 16384;

    // Pre-read epilogue x (fp16) from A stage jslab into regs (2 rows / u32).
    uint32_t xr[16];
    {
        const int s  = tid >> 6;
        const int j0 = tid & 63;
        #pragma unroll
        for (int q = 0; q < 16; ++q) {
            int r0 = s * 32 + 2 * q;
            uint32_t lo, hi;
            asm volatile("ld.shared.u16 %0, [%1];" : "=r"(lo)
                : "r"(sb + jslab * 16384 + SWZ128((uint32_t)(r0 * 128 + j0 * 2))));
            asm volatile("ld.shared.u16 %0, [%1];" : "=r"(hi)
                : "r"(sb + jslab * 16384 + SWZ128((uint32_t)((r0 + 1) * 128 + j0 * 2))));
            xr[q] = lo | (hi << 16);
        }
    }

    // Stage z (fp32) into the overlay regions.
    {
        int gate = warpN >> 1;
        int njb  = (warpN & 1) * 32;
        #pragma unroll
        for (int mt = 0; mt < 4; ++mt) {
            #pragma unroll
            for (int nt = 0; nt < 4; ++nt) {
                int row = warpM * 64 + mt * 16 + grp;
                int j   = njb + nt * 8 + 2 * lq;
                uint32_t base = zreg[gate][j >> 5];
                uint32_t off0 = SWZ128((uint32_t)(row * 128 + (j & 31) * 4));
                uint32_t off1 = SWZ128((uint32_t)((row + 8) * 128 + (j & 31) * 4));
                asm volatile("st.shared.v2.f32 [%0], {%1,%2};"
                    :: "r"(base + off0), "f"(c[mt][nt][0]), "f"(c[mt][nt][1]));
                asm volatile("st.shared.v2.f32 [%0], {%1,%2};"
                    :: "r"(base + off1), "f"(c[mt][nt][2]), "f"(c[mt][nt][3]));
            }
        }
    }
    __syncthreads();

    // Fused elementwise + per-segment scan (32 contiguous rows per thread).
    {
        const int s  = tid >> 6;          // segment 0..3
        const int j0 = tid & 63;
        const int d  = head * 256 + jslab * 64 + j0;
        const float bi = ig_b[d];
        const float ba = ag_b[d];
        const float sp8 = -8.f * g_sp[d];
        const float L2E = 1.44269504088896f;
        const uint32_t zi_base = zreg[0][j0 >> 5];
        const uint32_t za_base = zreg[1][j0 >> 5];
        const uint32_t joff = (j0 & 31) * 4;
        float* ga_out = g_a + (size_t)(m0 + s * 32) * Dd + d;
        __half* nx_out = g_nx + (size_t)(m0 + s * 32) * Dd + d;
        float A = 1.f, h = 0.f;
        #pragma unroll 4
        for (int it = 0; it < 32; ++it) {
            int row = s * 32 + it;
            float zi, za;
            asm volatile("ld.shared.f32 %0, [%1];" : "=f"(zi)
                : "r"(zi_base + SWZ128((uint32_t)(row * 128 + joff))));
            asm volatile("ld.shared.f32 %0, [%1];" : "=f"(za)
                : "r"(za_base + SWZ128((uint32_t)(row * 128 + joff))));
            zi += bi; za += ba;
            float gx = fmaf(tanha(0.5f * zi), 0.5f, 0.5f);
            float ga = fmaf(tanha(0.5f * za), 0.5f, 0.5f);
            float la = ga * sp8;
            float a, mult;
            asm("ex2.approx.f32 %0, %1;" : "=f"(a) : "f"(la * L2E));
            float m2 = fmaxf(fmaf(-a, a, 1.f), 0.f);
            asm("sqrt.approx.f32 %0, %1;" : "=f"(mult) : "f"(m2));
            uint32_t xbits = (xr[it >> 1] >> ((it & 1) * 16)) & 0xFFFFu;
            float xv = __half2float(__ushort_as_half((unsigned short)xbits));
            __half nxh = __float2half_rn(xv * gx * mult);
            float nx = __half2float(nxh);    // rounded value, consistent with scan
            ga_out[(size_t)it * Dd] = a;
            nx_out[(size_t)it * Dd] = nxh;
            h = fmaf(a, h, nx);
            A *= a;
        }
        float2* sseg = (float2*)(smem + (segb - sb));
        sseg[s * 64 + j0] = make_float2(A, h);
    }
    __syncthreads();
    if (tid < 64) {
        float2* sseg = (float2*)(smem + (segb - sb));
        float2 s0 = sseg[tid], s1 = sseg[64 + tid], s2 = sseg[128 + tid], s3 = sseg[192 + tid];
        float Ac = s0.x * s1.x * s2.x * s3.x;
        float hc = fmaf(s3.x, fmaf(s2.x, fmaf(s1.x, s0.y, s1.y), s2.y), s3.y);
        int b  = m0 >> 12;
        int ci = (m0 & 4095) >> 7;
        int dd = head * 256 + jslab * 64 + tid;
        g_chunkA[ci * BD + b * Dd + dd] = Ac;
        g_chunkH[ci * BD + b * Dd + dd] = hc;
    }
}

// ---------------------------------------------------------------------------
// Final scan: inline chunk-prefix (batched loads) + streaming chunk scan.
// ---------------------------------------------------------------------------
__global__ void scan_part3(const float* __restrict__ hidden, float* __restrict__ y,
                           float* __restrict__ hfinal, int write_h)
{
    int g  = blockIdx.x * blockDim.x + threadIdx.x;
    int ci = g / BD;                      // uniform within block
    int ch = g % BD;
    int b = ch / Dd, d = ch % Dd;

    // chunk-prefix: h at start of chunk ci
    float h = hidden[ch];
    {
        int k = 0;
        for (; k + 4 <= ci; k += 4) {
            float a0 = g_chunkA[(k+0) * BD + ch], h0 = g_chunkH[(k+0) * BD + ch];
            float a1 = g_chunkA[(k+1) * BD + ch], h1 = g_chunkH[(k+1) * BD + ch];
            float a2 = g_chunkA[(k+2) * BD + ch], h2 = g_chunkH[(k+2) * BD + ch];
            float a3 = g_chunkA[(k+3) * BD + ch], h3 = g_chunkH[(k+3) * BD + ch];
            h = fmaf(a0, h, h0);
            h = fmaf(a1, h, h1);
            h = fmaf(a2, h, h2);
            h = fmaf(a3, h, h3);
        }
        for (; k < ci; ++k)
            h = fmaf(g_chunkA[k * BD + ch], h, g_chunkH[k * BD + ch]);
    }

    size_t off = ((size_t)(b * Ll + ci * CLEN)) * Dd + d;
    const float* pa = g_a + off;
    const __half* pn = g_nx + off;
    float* yp = y + off;

    float ca[8], cn[8];
    #pragma unroll
    for (int i = 0; i < 8; ++i) {
        ca[i] = pa[(size_t)i * Dd];
        cn[i] = __half2float(pn[(size_t)i * Dd]);
    }
    #pragma unroll 1
    for (int base = 0; base < CLEN; base += 8) {
        float na[8], nn[8];
        if (base + 8 < CLEN) {
            #pragma unroll
            for (int i = 0; i < 8; ++i) {
                na[i] = pa[(size_t)(base + 8 + i) * Dd];
                nn[i] = __half2float(pn[(size_t)(base + 8 + i) * Dd]);
            }
        } else {
            #pragma unroll
            for (int i = 0; i < 8; ++i) { na[i] = 0.f; nn[i] = 0.f; }
        }
        #pragma unroll
        for (int i = 0; i < 8; ++i) {
            h = fmaf(ca[i], h, cn[i]);
            yp[(size_t)(base + i) * Dd] = h;
        }
        #pragma unroll
        for (int i = 0; i < 8; ++i) { ca[i] = na[i]; cn[i] = nn[i]; }
    }

    if (write_h && ci == CHUNKS - 1) hfinal[ch] = h;
}

extern "C" void kernel_launch(void* const* d_in, const int* in_sizes, int n_in,
                              void* d_out, int out_size)
{
    const float* x        = (const float*)d_in[0];
    const float* hidden   = (const float*)d_in[1];
    const float* a_param  = (const float*)d_in[2];
    const float* ig_w     = (const float*)d_in[3];
    const float* ig_b     = (const float*)d_in[4];
    const float* ag_w     = (const float*)d_in[5];
    const float* ag_b     = (const float*)d_in[6];
    float* y = (float*)d_out;

    int write_h = (out_size >= BLt * Dd + BD) ? 1 : 0;
    float* hf = y + (size_t)BLt * Dd;

    cudaFuncSetAttribute(gates_kernel, cudaFuncAttributeMaxDynamicSharedMemorySize, SMEM_TOTAL);

    prep_kernel<<<1024, 256>>>(ig_w, ag_w, a_param);
    gates_kernel<<<dim3(32, 128), 256, SMEM_TOTAL>>>(x, ig_b, ag_b);
    scan_part3<<<(BD * CHUNKS) / 256, 256>>>(hidden, y, hf, write_h);
}